// round 3
// baseline (speedup 1.0000x reference)
#include <cuda_runtime.h>
#include <cstdint>

typedef unsigned long long U64;

__device__ __forceinline__ U64 pack2(float x) {
    U64 r; asm("mov.b64 %0, {%1, %1};" : "=l"(r) : "f"(x)); return r;
}
__device__ __forceinline__ void fma2(U64 &acc, U64 a, U64 b) {
    asm("fma.rn.f32x2 %0, %1, %2, %0;" : "+l"(acc) : "l"(a), "l"(b));
}
__device__ __forceinline__ float hsum2(U64 a) {
    float lo, hi; asm("mov.b64 {%0,%1}, %2;" : "=f"(lo), "=f"(hi) : "l"(a));
    return lo + hi;
}
__device__ __forceinline__ float sigmoid_f(float x) {
    return 1.f / (1.f + __expf(-x));
}
__device__ __forceinline__ float tanh_exp(float x) {
    float e = __expf(2.f * x);
    return 1.f - __fdividef(2.f, e + 1.f);
}

#define B_    256
#define T_    1024
#define F_    128
#define UU    64
#define NPRE  320   // P cols: [Emu_x(64) | Elv_x(64) | Wg_x(192)]
#define NW1   512   // W1 cols: [hp(64) pmu(64) plv(64) qmu_h(64) qlv_h(64) mh(192)]

__device__ float g_Wc[F_ * NPRE];          // W_in @ [Emu_top | Elv_top | Wg_top]
__device__ float g_W1p[UU * NW1];          // k-pair-packed: [kp][2c+j] = W1[2kp+j][c]
__device__ float g_P[B_ * T_ * NPRE];      // precomputed input projections

// ---------------------------------------------------------------------------
// Prep A: g_Wc = W_in (128x128) @ [Emu[:128] | Elv[:128] | Wg[:128]]
// ---------------------------------------------------------------------------
__global__ void k_prep_wc(const float* __restrict__ Win,
                          const float* __restrict__ Emu,
                          const float* __restrict__ Elv,
                          const float* __restrict__ Wg) {
    int r = blockIdx.x;      // 0..127
    int c = threadIdx.x;     // 0..319
    float s = 0.f;
    if (c < 64) {
        for (int k = 0; k < F_; k++) s += Win[r*F_ + k] * Emu[k*64 + c];
    } else if (c < 128) {
        int j = c - 64;
        for (int k = 0; k < F_; k++) s += Win[r*F_ + k] * Elv[k*64 + j];
    } else {
        int j = c - 128;
        for (int k = 0; k < F_; k++) s += Win[r*F_ + k] * Wg[k*192 + j];
    }
    g_Wc[r*NPRE + c] = s;
}

// ---------------------------------------------------------------------------
// Prep B: W1 = [S | S@Pmu | S@Plv | S@Emu_bot | S@Elv_bot | S@R], written
// k-pair packed: g_W1p[(r>>1)*1024 + 2c + (r&1)] = W1[r][c]
// ---------------------------------------------------------------------------
__global__ void k_prep_w1(const float* __restrict__ S,
                          const float* __restrict__ Pmu,
                          const float* __restrict__ Plv,
                          const float* __restrict__ Emu,
                          const float* __restrict__ Elv,
                          const float* __restrict__ R) {
    int r = blockIdx.x;      // 0..63 (k index)
    int c = threadIdx.x;     // 0..511
    float v;
    if (c < 64) {
        v = S[r*64 + c];
    } else {
        int j = c - 64;
        float s = 0.f;
        if (j < 64)       { for (int k = 0; k < 64; k++) s += S[r*64+k] * Pmu[k*64 + j]; }
        else if (j < 128) { int jj = j-64;  for (int k = 0; k < 64; k++) s += S[r*64+k] * Plv[k*64 + jj]; }
        else if (j < 192) { int jj = j-128; for (int k = 0; k < 64; k++) s += S[r*64+k] * Emu[(128+k)*64 + jj]; }
        else if (j < 256) { int jj = j-192; for (int k = 0; k < 64; k++) s += S[r*64+k] * Elv[(128+k)*64 + jj]; }
        else              { int jj = j-256; for (int k = 0; k < 64; k++) s += S[r*64+k] * R[k*192 + jj]; }
        v = s;
    }
    g_W1p[(r >> 1) * 1024 + 2*c + (r & 1)] = v;
}

// ---------------------------------------------------------------------------
// GEMM: g_P[m][n] = sum_k x[m][k] * g_Wc[k][n]   (M=262144, K=128, N=320)
// K-SIMD f32x2: per-thread 4 rows x 8 cols, acc {even-k, odd-k}.
// ---------------------------------------------------------------------------
#define GBM 128
#define GBN 64
#define SA_STRIDE 130   // conflict-free for U64 k-pair reads; even (U64 aligned)
#define GEMM_SMEM_BYTES ((GBM*SA_STRIDE + 64*128) * 4)

__global__ void __launch_bounds__(256, 2) k_gemm_p(const float* __restrict__ x) {
    extern __shared__ float sm[];
    float* sA  = sm;                      // [128][130]  row-major (k contiguous)
    float* sBp = sm + GBM * SA_STRIDE;    // [64 kp][128] : [kp][2c+j] = B[2kp+j][c]
    int tid = threadIdx.x;
    int mb = blockIdx.x * GBM;
    int nb = blockIdx.y * GBN;

    // fill A: float4 gmem loads -> 2x STS.64 (stride 130 is not float4-aligned)
    for (int i = tid; i < 128 * 32; i += 256) {
        int r = i >> 5, c4 = (i & 31) << 2;
        float4 v = *(const float4*)(x + (mb + r) * F_ + c4);
        float* d = sA + r * SA_STRIDE + c4;
        *(float2*)d = make_float2(v.x, v.y);
        *(float2*)(d + 2) = make_float2(v.z, v.w);
    }
    // fill B k-pair packed
    for (int i = tid; i < 128 * 16; i += 256) {
        int k = i >> 4, c4 = (i & 15) << 2;
        float4 v = *(const float4*)(g_Wc + k * NPRE + nb + c4);
        float* d = sBp + (k >> 1) * 128 + (k & 1);
        d[2*(c4+0)] = v.x; d[2*(c4+1)] = v.y;
        d[2*(c4+2)] = v.z; d[2*(c4+3)] = v.w;
    }
    __syncthreads();

    int cg = tid & 7, rg = tid >> 3;
    int c0 = cg << 3;        // 8 contiguous cols
    int r0 = rg << 2;        // 4 rows

    U64 acc[4][8];
#pragma unroll
    for (int i = 0; i < 4; i++)
#pragma unroll
        for (int j = 0; j < 8; j++) acc[i][j] = 0ull;

#pragma unroll 4
    for (int kp = 0; kp < 64; kp++) {
        U64 a0 = *(const U64*)(sA + (r0+0)*SA_STRIDE + 2*kp);
        U64 a1 = *(const U64*)(sA + (r0+1)*SA_STRIDE + 2*kp);
        U64 a2 = *(const U64*)(sA + (r0+2)*SA_STRIDE + 2*kp);
        U64 a3 = *(const U64*)(sA + (r0+3)*SA_STRIDE + 2*kp);
        const float* bp = sBp + kp * 128 + (c0 << 1);
        ulonglong2 q0 = *(const ulonglong2*)(bp);
        ulonglong2 q1 = *(const ulonglong2*)(bp + 4);
        ulonglong2 q2 = *(const ulonglong2*)(bp + 8);
        ulonglong2 q3 = *(const ulonglong2*)(bp + 12);
        fma2(acc[0][0], a0, q0.x); fma2(acc[0][1], a0, q0.y);
        fma2(acc[0][2], a0, q1.x); fma2(acc[0][3], a0, q1.y);
        fma2(acc[0][4], a0, q2.x); fma2(acc[0][5], a0, q2.y);
        fma2(acc[0][6], a0, q3.x); fma2(acc[0][7], a0, q3.y);
        fma2(acc[1][0], a1, q0.x); fma2(acc[1][1], a1, q0.y);
        fma2(acc[1][2], a1, q1.x); fma2(acc[1][3], a1, q1.y);
        fma2(acc[1][4], a1, q2.x); fma2(acc[1][5], a1, q2.y);
        fma2(acc[1][6], a1, q3.x); fma2(acc[1][7], a1, q3.y);
        fma2(acc[2][0], a2, q0.x); fma2(acc[2][1], a2, q0.y);
        fma2(acc[2][2], a2, q1.x); fma2(acc[2][3], a2, q1.y);
        fma2(acc[2][4], a2, q2.x); fma2(acc[2][5], a2, q2.y);
        fma2(acc[2][6], a2, q3.x); fma2(acc[2][7], a2, q3.y);
        fma2(acc[3][0], a3, q0.x); fma2(acc[3][1], a3, q0.y);
        fma2(acc[3][2], a3, q1.x); fma2(acc[3][3], a3, q1.y);
        fma2(acc[3][4], a3, q2.x); fma2(acc[3][5], a3, q2.y);
        fma2(acc[3][6], a3, q3.x); fma2(acc[3][7], a3, q3.y);
    }

#pragma unroll
    for (int i = 0; i < 4; i++) {
        float4 v0, v1;
        v0.x = hsum2(acc[i][0]); v0.y = hsum2(acc[i][1]);
        v0.z = hsum2(acc[i][2]); v0.w = hsum2(acc[i][3]);
        v1.x = hsum2(acc[i][4]); v1.y = hsum2(acc[i][5]);
        v1.z = hsum2(acc[i][6]); v1.w = hsum2(acc[i][7]);
        float* dst = g_P + (mb + r0 + i) * NPRE + nb + c0;
        *(float4*)dst = v0;
        *(float4*)(dst + 4) = v1;
    }
}

// ---------------------------------------------------------------------------
// Recurrent kernel v3: W1 in registers as k-pair-packed f32x2 (2 cols/thread),
// h plain in smem (one LDS.128 = 4 k-values), K-SIMD accumulators.
// ---------------------------------------------------------------------------
#define OFF_W2  0              // [64][192]
#define OFF_B0  12288          // [192]
#define OFF_B1  12480          // [192]
#define OFF_Y   12672          // [2][512]
#define OFF_P   13696          // [2][320]
#define OFF_G   14336          // [4][192]
#define OFF_H   15104          // [2][64] plain h (16B aligned)
#define OFF_Z2  15232          // U64 [2][64] dup'd z
#define RNN_SMEM_FLOATS 15488
#define RNN_SMEM_BYTES  (RNN_SMEM_FLOATS * 4)

__global__ void __launch_bounds__(256, 1) k_rnn(const float* __restrict__ gbias,
                                                const float* __restrict__ gruk,
                                                float* __restrict__ out) {
    extern __shared__ float sm[];
    float* sW2 = sm + OFF_W2;
    float* sB0 = sm + OFF_B0;
    float* sB1 = sm + OFF_B1;
    float* sY  = sm + OFF_Y;
    float* sP  = sm + OFF_P;
    float* sG  = sm + OFF_G;
    float* sH  = sm + OFF_H;            // [2][64] plain
    U64*   sZ2 = (U64*)(sm + OFF_Z2);   // [2][64] dup'd

    int tid = threadIdx.x;
    int b0  = blockIdx.x * 2;

    // --- W2 (gru_kernel rows 128..191), biases; zero h ---
    for (int i = tid; i < (64*192)/4; i += 256)
        *(float4*)(sW2 + i*4) = *(const float4*)(gruk + 128*192 + i*4);
    if (tid < 96)
        *(float4*)(sB0 + tid*4) = *(const float4*)(gbias + tid*4);
    if (tid < 128) sH[tid] = 0.f;

    // --- W1 regs: thread owns cols c0=2t, c0+1; k-pair packed ---
    U64 w1a[32], w1b[32];
#pragma unroll
    for (int i = 0; i < 32; i++) {
        ulonglong2 v = *(const ulonglong2*)(g_W1p + i * 1024 + (tid << 2));
        w1a[i] = v.x; w1b[i] = v.y;
    }

    // per-thread constant mappings
    int re = tid >> 6;                       // eltwise row (tid<128)
    int ue = tid & 63;
    int hf = (tid < 96) ? 0 : 1;             // M2 K-half
    int j2 = (tid < 96) ? tid : (tid - 96);
    int kb = hf << 5;
    int rp = (tid < 160) ? (tid / 80) : 0;   // P-prefetch row
    int jp = (tid < 160) ? ((tid - rp*80) << 2) : 0;

    const int SEQ = B_ * T_ * UU;
    __syncthreads();

#pragma unroll 1
    for (int t = 0; t < T_; t++) {
        float4 pv;
        if (tid < 160)
            pv = *(const float4*)(g_P + ((b0 + rp) * T_ + t) * NPRE + jp);

        // ---- M1: Y[r][c0..c0+1] via K-SIMD. One LDS.128 = 4 k's of one row.
        const ulonglong2* h0 = (const ulonglong2*)(sH);
        const ulonglong2* h1 = (const ulonglong2*)(sH + 64);
        U64 a00 = 0ull, a01 = 0ull, a10 = 0ull, a11 = 0ull;
#pragma unroll
        for (int i = 0; i < 16; i++) {
            ulonglong2 ha = h0[i];     // {h0[4i],h0[4i+1]},{h0[4i+2],h0[4i+3]}
            ulonglong2 hb = h1[i];
            fma2(a00, ha.x, w1a[2*i]);   fma2(a01, ha.x, w1b[2*i]);
            fma2(a10, hb.x, w1a[2*i]);   fma2(a11, hb.x, w1b[2*i]);
            fma2(a00, ha.y, w1a[2*i+1]); fma2(a01, ha.y, w1b[2*i+1]);
            fma2(a10, hb.y, w1a[2*i+1]); fma2(a11, hb.y, w1b[2*i+1]);
        }
        {
            float2 y0 = make_float2(hsum2(a00), hsum2(a01));
            float2 y1 = make_float2(hsum2(a10), hsum2(a11));
            *(float2*)(sY + (tid << 1))       = y0;
            *(float2*)(sY + 512 + (tid << 1)) = y1;
        }
        if (tid < 160) *(float4*)(sP + rp*320 + jp) = pv;
        __syncthreads();

        // ---- elt1: z + outputs
        if (tid < 128) {
            const float* Yr = sY + (re << 9);
            const float* Pr = sP + re * 320;
            float pmu = Yr[64 + ue];
            float plv = Yr[128 + ue];
            float qmu = Yr[192 + ue] + Pr[ue];
            float qlv = Yr[256 + ue] + Pr[64 + ue];
            float z   = 0.5f * __expf(qlv) + qmu;
            sZ2[(re << 6) + ue] = pack2(z);
            int base = ((b0 + re) * T_ + t) * UU + ue;
            out[base]         = z;
            out[base + SEQ]   = qmu;
            out[base + 2*SEQ] = pmu;
            out[base + 3*SEQ] = qlv;
            out[base + 4*SEQ] = plv;
        }
        __syncthreads();

        // ---- M2: G_half[hf][r][2j..2j+1] = sum_{k in half} z[r][k]*W2[k][..]
        if (tid < 192) {
            U64 g0 = 0ull, g1 = 0ull;
            const float* w2 = sW2 + (j2 << 1);
#pragma unroll
            for (int kk = 0; kk < 32; kk += 2) {
                int k = kb + kk;
                ulonglong2 z0 = *(const ulonglong2*)(sZ2 + k);
                ulonglong2 z1 = *(const ulonglong2*)(sZ2 + 64 + k);
                U64 wa = *(const U64*)(w2 + k * 192);
                U64 wb = *(const U64*)(w2 + (k+1) * 192);
                fma2(g0, z0.x, wa); fma2(g1, z1.x, wa);
                fma2(g0, z0.y, wb); fma2(g1, z1.y, wb);
            }
            *(U64*)(sG + ((hf << 1) + 0) * 192 + (j2 << 1)) = g0;
            *(U64*)(sG + ((hf << 1) + 1) * 192 + (j2 << 1)) = g1;
        }
        __syncthreads();

        // ---- elt2: gates -> h_new (plain store)
        if (tid < 128) {
            const float* Yr = sY + (re << 9);
            const float* Pr = sP + re * 320;
            const float* Ga = sG + re * 192;
            const float* Gb = sG + (2 + re) * 192;
            float hp  = Yr[ue];
            float mxz = Pr[128 + ue] + Ga[ue]       + Gb[ue]       + sB0[ue];
            float mxr = Pr[192 + ue] + Ga[64 + ue]  + Gb[64 + ue]  + sB0[64 + ue];
            float mxh = Pr[256 + ue] + Ga[128 + ue] + Gb[128 + ue] + sB0[128 + ue];
            float mhz = Yr[320 + ue] + sB1[ue];
            float mhr = Yr[384 + ue] + sB1[64 + ue];
            float mhh = Yr[448 + ue] + sB1[128 + ue];
            float zt = sigmoid_f(mxz + mhz);
            float rt = sigmoid_f(mxr + mhr);
            float hh = tanh_exp(mxh + rt * mhh);
            sH[(re << 6) + ue] = zt * hp + (1.f - zt) * hh;
        }
        __syncthreads();
    }
}

// ---------------------------------------------------------------------------
extern "C" void kernel_launch(void* const* d_in, const int* in_sizes, int n_in,
                              void* d_out, int out_size) {
    const float* x   = (const float*)d_in[0];
    const float* Win = (const float*)d_in[1];
    const float* S   = (const float*)d_in[2];
    const float* Emu = (const float*)d_in[3];
    const float* Elv = (const float*)d_in[4];
    const float* Pmu = (const float*)d_in[5];
    const float* Plv = (const float*)d_in[6];
    const float* Wg  = (const float*)d_in[7];
    const float* R   = (const float*)d_in[8];
    const float* gb  = (const float*)d_in[9];

    cudaFuncSetAttribute(k_gemm_p, cudaFuncAttributeMaxDynamicSharedMemorySize, GEMM_SMEM_BYTES);
    cudaFuncSetAttribute(k_rnn,    cudaFuncAttributeMaxDynamicSharedMemorySize, RNN_SMEM_BYTES);

    k_prep_wc<<<128, 320>>>(Win, Emu, Elv, Wg);
    k_prep_w1<<<64, 512>>>(S, Pmu, Plv, Emu, Elv, R);

    dim3 gg(2048, 5);
    k_gemm_p<<<gg, 256, GEMM_SMEM_BYTES>>>(x);

    k_rnn<<<128, 256, RNN_SMEM_BYTES>>>(gb, Wg, (float*)d_out);
}

// round 4
// speedup vs baseline: 1.3970x; 1.3970x over previous
#include <cuda_runtime.h>
#include <cstdint>

typedef unsigned long long U64;

__device__ __forceinline__ U64 pack2(float x) {
    U64 r; asm("mov.b64 %0, {%1, %1};" : "=l"(r) : "f"(x)); return r;
}
__device__ __forceinline__ void fma2(U64 &acc, U64 a, U64 b) {
    asm("fma.rn.f32x2 %0, %1, %2, %0;" : "+l"(acc) : "l"(a), "l"(b));
}
__device__ __forceinline__ float hsum2(U64 a) {
    float lo, hi; asm("mov.b64 {%0,%1}, %2;" : "=f"(lo), "=f"(hi) : "l"(a));
    return lo + hi;
}
__device__ __forceinline__ float sigmoid_f(float x) {
    return 1.f / (1.f + __expf(-x));
}
__device__ __forceinline__ float tanh_exp(float x) {
    float e = __expf(2.f * x);
    return 1.f - __fdividef(2.f, e + 1.f);
}

#define B_    256
#define T_    1024
#define F_    128
#define UU    64
#define NPRE  320   // P cols: [Emu_x(64) | Elv_x(64) | Wg_x(192)]
#define NW1   512

__device__ float g_Wc[F_ * NPRE];
__device__ float g_W1p[UU * NW1];          // k-pair + thread-role permuted (see prep)
__device__ float g_P[B_ * T_ * NPRE];

// ---------------------------------------------------------------------------
// Prep A: g_Wc = W_in (128x128) @ [Emu[:128] | Elv[:128] | Wg[:128]]
// ---------------------------------------------------------------------------
__global__ void k_prep_wc(const float* __restrict__ Win,
                          const float* __restrict__ Emu,
                          const float* __restrict__ Elv,
                          const float* __restrict__ Wg) {
    int r = blockIdx.x;
    int c = threadIdx.x;
    float s = 0.f;
    if (c < 64) {
        for (int k = 0; k < F_; k++) s += Win[r*F_ + k] * Emu[k*64 + c];
    } else if (c < 128) {
        int j = c - 64;
        for (int k = 0; k < F_; k++) s += Win[r*F_ + k] * Elv[k*64 + j];
    } else {
        int j = c - 128;
        for (int k = 0; k < F_; k++) s += Win[r*F_ + k] * Wg[k*192 + j];
    }
    g_Wc[r*NPRE + c] = s;
}

// ---------------------------------------------------------------------------
// Prep B: W1 = [S | S@Pmu | S@Plv | S@Emu_bot | S@Elv_bot | S@R] with original
// cols [hp(0:64) pmu(64:128) plv(128:192) qmu(192:256) qlv(256:320) mh(320:512)].
// Stored k-pair packed AND column-permuted so that kernel thread t owns:
//   t<64:        (qmu[t],  qlv[t])
//   64<=t<128:   (pmu[u],  plv[u])   u=t-64
//   128<=t<160:  (hp[2j],  hp[2j+1]) j=t-128
//   160<=t<256:  (mh[2j],  mh[2j+1]) j=t-160
// Entry index: g_W1p[(r>>1)*1024 + 2*slot + (r&1)], slot = 2*t (colA) / 2*t+1 (colB)
// ---------------------------------------------------------------------------
__global__ void k_prep_w1(const float* __restrict__ S,
                          const float* __restrict__ Pmu,
                          const float* __restrict__ Plv,
                          const float* __restrict__ Emu,
                          const float* __restrict__ Elv,
                          const float* __restrict__ R) {
    int r = blockIdx.x;      // k index 0..63
    int c = threadIdx.x;     // original col 0..511
    float v;
    if (c < 64) {
        v = S[r*64 + c];
    } else {
        int j = c - 64;
        float s = 0.f;
        if (j < 64)       { for (int k = 0; k < 64; k++) s += S[r*64+k] * Pmu[k*64 + j]; }
        else if (j < 128) { int jj = j-64;  for (int k = 0; k < 64; k++) s += S[r*64+k] * Plv[k*64 + jj]; }
        else if (j < 192) { int jj = j-128; for (int k = 0; k < 64; k++) s += S[r*64+k] * Emu[(128+k)*64 + jj]; }
        else if (j < 256) { int jj = j-192; for (int k = 0; k < 64; k++) s += S[r*64+k] * Elv[(128+k)*64 + jj]; }
        else              { int jj = j-256; for (int k = 0; k < 64; k++) s += S[r*64+k] * R[k*192 + jj]; }
        v = s;
    }
    int slot;
    if      (c < 64)  slot = 2*(128 + (c >> 1)) + (c & 1);          // hp -> t 128..159
    else if (c < 128) slot = 2*(64 + (c - 64));                     // pmu colA, t 64..127
    else if (c < 192) slot = 2*(64 + (c - 128)) + 1;                // plv colB
    else if (c < 256) slot = 2*(c - 192);                           // qmu colA, t 0..63
    else if (c < 320) slot = 2*(c - 256) + 1;                       // qlv colB
    else              slot = 2*(160 + ((c - 320) >> 1)) + ((c - 320) & 1); // mh -> t 160..255
    g_W1p[(r >> 1) * 1024 + 2*slot + (r & 1)] = v;
}

// ---------------------------------------------------------------------------
// GEMM (round-2 version, verbatim — measured good)
// ---------------------------------------------------------------------------
#define GBM 128
#define GBN 64
#define SA_STRIDE 132
#define GEMM_SMEM_BYTES ((128*SA_STRIDE + 128*GBN) * 4)

__global__ void __launch_bounds__(256, 2) k_gemm_p(const float* __restrict__ x) {
    extern __shared__ float sm[];
    float* sA = sm;
    float* sB = sm + 128 * SA_STRIDE;
    int tid = threadIdx.x;
    int mb = blockIdx.x * GBM;
    int nb = blockIdx.y * GBN;

    for (int i = tid; i < 128 * 32; i += 256) {
        int r = i >> 5, c4 = (i & 31) << 2;
        float4 v = *(const float4*)(x + (mb + r) * F_ + c4);
        *(float4*)(sA + r * SA_STRIDE + c4) = v;
    }
    for (int i = tid; i < 128 * 16; i += 256) {
        int k = i >> 4, c4 = (i & 15) << 2;
        *(float4*)(sB + k * GBN + c4) = *(const float4*)(g_Wc + k * NPRE + nb + c4);
    }
    __syncthreads();

    int cg = tid & 7, rg = tid >> 3;
    int c0 = cg << 3, r0 = rg << 2;

    U64 acc[4][4];
#pragma unroll
    for (int i = 0; i < 4; i++)
#pragma unroll
        for (int j = 0; j < 4; j++) acc[i][j] = 0ull;

#pragma unroll 4
    for (int k = 0; k < 128; k++) {
        float a0 = sA[(r0+0)*SA_STRIDE + k];
        float a1 = sA[(r0+1)*SA_STRIDE + k];
        float a2 = sA[(r0+2)*SA_STRIDE + k];
        float a3 = sA[(r0+3)*SA_STRIDE + k];
        ulonglong2 b01 = *(const ulonglong2*)(sB + k*GBN + c0);
        ulonglong2 b23 = *(const ulonglong2*)(sB + k*GBN + c0 + 4);
        U64 p0 = pack2(a0), p1 = pack2(a1), p2 = pack2(a2), p3 = pack2(a3);
        fma2(acc[0][0], p0, b01.x); fma2(acc[0][1], p0, b01.y);
        fma2(acc[0][2], p0, b23.x); fma2(acc[0][3], p0, b23.y);
        fma2(acc[1][0], p1, b01.x); fma2(acc[1][1], p1, b01.y);
        fma2(acc[1][2], p1, b23.x); fma2(acc[1][3], p1, b23.y);
        fma2(acc[2][0], p2, b01.x); fma2(acc[2][1], p2, b01.y);
        fma2(acc[2][2], p2, b23.x); fma2(acc[2][3], p2, b23.y);
        fma2(acc[3][0], p3, b01.x); fma2(acc[3][1], p3, b01.y);
        fma2(acc[3][2], p3, b23.x); fma2(acc[3][3], p3, b23.y);
    }

#pragma unroll
    for (int i = 0; i < 4; i++) {
        float* dst = g_P + (mb + r0 + i) * NPRE + nb + c0;
        ulonglong2 v0; v0.x = acc[i][0]; v0.y = acc[i][1];
        *(ulonglong2*)dst = v0;
        ulonglong2 v1; v1.x = acc[i][2]; v1.y = acc[i][3];
        *(ulonglong2*)(dst + 4) = v1;
    }
}

// ---------------------------------------------------------------------------
// Recurrent kernel v4: 3 phases/step (elt1 folded into M1 via column perm),
// P loaded straight into registers (double-buffered one step ahead).
// ---------------------------------------------------------------------------
#define OFF_W2  0              // [64][192]
#define OFF_B0  12288          // [192]
#define OFF_B1  12480          // [192]
#define OFF_HP  12672          // [2][64]
#define OFF_MH  12800          // [2][192]
#define OFF_G   13184          // [4][192]
#define OFF_H   13952          // [2][64]
#define OFF_Z2  14080          // U64 [2][64] (byte 56320, 16B aligned)
#define RNN_SMEM_FLOATS 14336
#define RNN_SMEM_BYTES  (RNN_SMEM_FLOATS * 4)

__global__ void __launch_bounds__(256, 1) k_rnn(const float* __restrict__ gbias,
                                                const float* __restrict__ gruk,
                                                float* __restrict__ out) {
    extern __shared__ float sm[];
    float* sW2 = sm + OFF_W2;
    float* sB0 = sm + OFF_B0;
    float* sB1 = sm + OFF_B1;
    float* sHP = sm + OFF_HP;
    float* sMH = sm + OFF_MH;
    float* sG  = sm + OFF_G;
    float* sH  = sm + OFF_H;
    U64*   sZ2 = (U64*)(sm + OFF_Z2);

    int tid = threadIdx.x;
    int b0  = blockIdx.x * 2;

    for (int i = tid; i < (64*192)/4; i += 256)
        *(float4*)(sW2 + i*4) = *(const float4*)(gruk + 128*192 + i*4);
    if (tid < 96)
        *(float4*)(sB0 + tid*4) = *(const float4*)(gbias + tid*4);
    if (tid < 128) sH[tid] = 0.f;

    // W1 registers: thread t's two permuted columns, k-pair packed
    U64 w1a[32], w1b[32];
#pragma unroll
    for (int i = 0; i < 32; i++) {
        ulonglong2 v = *(const ulonglong2*)(g_W1p + i * 1024 + (tid << 2));
        w1a[i] = v.x; w1b[i] = v.y;
    }

    int re = tid >> 6, ue = tid & 63;
    int hf = (tid < 96) ? 0 : 1;
    int j2 = (tid < 96) ? tid : (tid - 96);
    int kb = hf << 5;

    const int SEQ = B_ * T_ * UU;
    // P base pointers (per-role)
    const float* PZ0 = g_P + (long)(b0)     * T_ * NPRE + tid;          // row0, col u / 64+u
    const float* PZ1 = g_P + (long)(b0 + 1) * T_ * NPRE + tid;
    const float* PG  = g_P + (long)(b0 + re)* T_ * NPRE + 128 + ue;     // gate cols

    // current / next P registers
    float cz0=0,cz1=0,cz2=0,cz3=0, cg0=0,cg1=0,cg2=0;
    if (tid < 64) {
        cz0 = PZ0[0];  cz1 = PZ0[64];
        cz2 = PZ1[0];  cz3 = PZ1[64];
    }
    if (tid < 128) {
        cg0 = PG[0];   cg1 = PG[64];  cg2 = PG[128];
    }
    __syncthreads();

#pragma unroll 1
    for (int t = 0; t < T_; t++) {
        // issue next-step P loads (clamped last iter; values unused then)
        int tn = (t + 1 < T_) ? (t + 1) : t;
        long offn = (long)tn * NPRE;
        float nz0=0,nz1=0,nz2=0,nz3=0, ng0=0,ng1=0,ng2=0;
        if (tid < 64) {
            nz0 = PZ0[offn];      nz1 = PZ0[offn + 64];
            nz2 = PZ1[offn];      nz3 = PZ1[offn + 64];
        }
        if (tid < 128) {
            ng0 = PG[offn];  ng1 = PG[offn + 64];  ng2 = PG[offn + 128];
        }

        // ---- M1: both rows, this thread's 2 cols, K-SIMD
        const ulonglong2* h0 = (const ulonglong2*)(sH);
        const ulonglong2* h1 = (const ulonglong2*)(sH + 64);
        U64 a00 = 0ull, a01 = 0ull, a10 = 0ull, a11 = 0ull;
#pragma unroll
        for (int i = 0; i < 16; i++) {
            ulonglong2 ha = h0[i];
            ulonglong2 hb = h1[i];
            fma2(a00, ha.x, w1a[2*i]);   fma2(a01, ha.x, w1b[2*i]);
            fma2(a10, hb.x, w1a[2*i]);   fma2(a11, hb.x, w1b[2*i]);
            fma2(a00, ha.y, w1a[2*i+1]); fma2(a01, ha.y, w1b[2*i+1]);
            fma2(a10, hb.y, w1a[2*i+1]); fma2(a11, hb.y, w1b[2*i+1]);
        }
        float y00 = hsum2(a00), y01 = hsum2(a01);
        float y10 = hsum2(a10), y11 = hsum2(a11);

        // ---- role-specific epilogue (former elt1, now in-register)
        if (tid < 64) {
            // (qmu, qlv) -> z, outputs for both rows
            float qmu0 = y00 + cz0, qlv0 = y01 + cz1;
            float qmu1 = y10 + cz2, qlv1 = y11 + cz3;
            float z0 = 0.5f * __expf(qlv0) + qmu0;
            float z1 = 0.5f * __expf(qlv1) + qmu1;
            sZ2[tid]      = pack2(z0);
            sZ2[64 + tid] = pack2(z1);
            int base0 = (b0 * T_ + t) * UU + tid;
            int base1 = base0 + T_ * UU;
            out[base0]          = z0;
            out[base0 + SEQ]    = qmu0;
            out[base0 + 3*SEQ]  = qlv0;
            out[base1]          = z1;
            out[base1 + SEQ]    = qmu1;
            out[base1 + 3*SEQ]  = qlv1;
        } else if (tid < 128) {
            int u = tid - 64;
            int base0 = (b0 * T_ + t) * UU + u;
            int base1 = base0 + T_ * UU;
            out[base0 + 2*SEQ] = y00;   // pmu row0
            out[base0 + 4*SEQ] = y01;   // plv row0
            out[base1 + 2*SEQ] = y10;
            out[base1 + 4*SEQ] = y11;
        } else if (tid < 160) {
            int j = tid - 128;
            *(float2*)(sHP + 2*j)       = make_float2(y00, y01);
            *(float2*)(sHP + 64 + 2*j)  = make_float2(y10, y11);
        } else {
            int j = tid - 160;
            *(float2*)(sMH + 2*j)        = make_float2(y00, y01);
            *(float2*)(sMH + 192 + 2*j)  = make_float2(y10, y11);
        }
        __syncthreads();

        // ---- M2: G_half[hf][r][2j..2j+1] = sum_{k in half} z[r][k]*W2[k][..]
        if (tid < 192) {
            U64 g0 = 0ull, g1 = 0ull;
            const float* w2 = sW2 + (j2 << 1);
#pragma unroll
            for (int kk = 0; kk < 32; kk += 2) {
                int k = kb + kk;
                ulonglong2 z0 = *(const ulonglong2*)(sZ2 + k);
                ulonglong2 z1 = *(const ulonglong2*)(sZ2 + 64 + k);
                U64 wa = *(const U64*)(w2 + k * 192);
                U64 wb = *(const U64*)(w2 + (k+1) * 192);
                fma2(g0, z0.x, wa); fma2(g1, z1.x, wa);
                fma2(g0, z0.y, wb); fma2(g1, z1.y, wb);
            }
            *(U64*)(sG + ((hf << 1) + 0) * 192 + (j2 << 1)) = g0;
            *(U64*)(sG + ((hf << 1) + 1) * 192 + (j2 << 1)) = g1;
        }
        __syncthreads();

        // ---- elt2: gates -> h_new
        if (tid < 128) {
            const float* Ga = sG + re * 192;
            const float* Gb = sG + (2 + re) * 192;
            float hp  = sHP[re * 64 + ue];
            float mhz = sMH[re * 192 + ue]        + sB1[ue];
            float mhr = sMH[re * 192 + 64 + ue]   + sB1[64 + ue];
            float mhh = sMH[re * 192 + 128 + ue]  + sB1[128 + ue];
            float mxz = cg0 + Ga[ue]        + Gb[ue]        + sB0[ue];
            float mxr = cg1 + Ga[64 + ue]   + Gb[64 + ue]   + sB0[64 + ue];
            float mxh = cg2 + Ga[128 + ue]  + Gb[128 + ue]  + sB0[128 + ue];
            float zt = sigmoid_f(mxz + mhz);
            float rt = sigmoid_f(mxr + mhr);
            float hh = tanh_exp(mxh + rt * mhh);
            sH[re * 64 + ue] = zt * hp + (1.f - zt) * hh;
        }
        __syncthreads();

        cz0 = nz0; cz1 = nz1; cz2 = nz2; cz3 = nz3;
        cg0 = ng0; cg1 = ng1; cg2 = ng2;
    }
}

// ---------------------------------------------------------------------------
extern "C" void kernel_launch(void* const* d_in, const int* in_sizes, int n_in,
                              void* d_out, int out_size) {
    const float* x   = (const float*)d_in[0];
    const float* Win = (const float*)d_in[1];
    const float* S   = (const float*)d_in[2];
    const float* Emu = (const float*)d_in[3];
    const float* Elv = (const float*)d_in[4];
    const float* Pmu = (const float*)d_in[5];
    const float* Plv = (const float*)d_in[6];
    const float* Wg  = (const float*)d_in[7];
    const float* R   = (const float*)d_in[8];
    const float* gb  = (const float*)d_in[9];

    cudaFuncSetAttribute(k_gemm_p, cudaFuncAttributeMaxDynamicSharedMemorySize, GEMM_SMEM_BYTES);
    cudaFuncSetAttribute(k_rnn,    cudaFuncAttributeMaxDynamicSharedMemorySize, RNN_SMEM_BYTES);

    k_prep_wc<<<128, 320>>>(Win, Emu, Elv, Wg);
    k_prep_w1<<<64, 512>>>(S, Pmu, Plv, Emu, Elv, R);

    dim3 gg(2048, 5);
    k_gemm_p<<<gg, 256, GEMM_SMEM_BYTES>>>(x);

    k_rnn<<<128, 256, RNN_SMEM_BYTES>>>(gb, Wg, (float*)d_out);
}

// round 5
// speedup vs baseline: 1.4221x; 1.0180x over previous
#include <cuda_runtime.h>
#include <cstdint>

typedef unsigned long long U64;

__device__ __forceinline__ U64 pack2(float x) {
    U64 r; asm("mov.b64 %0, {%1, %1};" : "=l"(r) : "f"(x)); return r;
}
__device__ __forceinline__ void fma2(U64 &acc, U64 a, U64 b) {
    asm("fma.rn.f32x2 %0, %1, %2, %0;" : "+l"(acc) : "l"(a), "l"(b));
}
__device__ __forceinline__ float hsum2(U64 a) {
    float lo, hi; asm("mov.b64 {%0,%1}, %2;" : "=f"(lo), "=f"(hi) : "l"(a));
    return lo + hi;
}
__device__ __forceinline__ float sigmoid_f(float x) {
    return 1.f / (1.f + __expf(-x));
}
__device__ __forceinline__ float tanh_exp(float x) {
    float e = __expf(2.f * x);
    return 1.f - __fdividef(2.f, e + 1.f);
}

#define B_    256
#define T_    1024
#define F_    128
#define UU    64
#define NPRE  320   // P cols: [Emu_x(64) | Elv_x(64) | Wg_x(192)]
#define NW1   512

__device__ float g_Wc[F_ * NPRE];
__device__ float g_W1p[UU * NW1];          // k-pair + thread-role permuted (see prep)
__device__ float g_P[B_ * T_ * NPRE];

// ---------------------------------------------------------------------------
// Prep A: g_Wc = W_in (128x128) @ [Emu[:128] | Elv[:128] | Wg[:128]]
// ---------------------------------------------------------------------------
__global__ void k_prep_wc(const float* __restrict__ Win,
                          const float* __restrict__ Emu,
                          const float* __restrict__ Elv,
                          const float* __restrict__ Wg) {
    int r = blockIdx.x;
    int c = threadIdx.x;
    float s = 0.f;
    if (c < 64) {
        for (int k = 0; k < F_; k++) s += Win[r*F_ + k] * Emu[k*64 + c];
    } else if (c < 128) {
        int j = c - 64;
        for (int k = 0; k < F_; k++) s += Win[r*F_ + k] * Elv[k*64 + j];
    } else {
        int j = c - 128;
        for (int k = 0; k < F_; k++) s += Win[r*F_ + k] * Wg[k*192 + j];
    }
    g_Wc[r*NPRE + c] = s;
}

// ---------------------------------------------------------------------------
// Prep B: W1 = [S | S@Pmu | S@Plv | S@Emu_bot | S@Elv_bot | S@R] with original
// cols [hp(0:64) pmu(64:128) plv(128:192) qmu(192:256) qlv(256:320) mh(320:512)].
// k-pair packed + column-permuted; thread t owns:
//   t<64: (qmu[t], qlv[t]);  64..127: (pmu[u], plv[u]);
//   128..159: (hp[2j], hp[2j+1]);  160..255: (mh[2j], mh[2j+1])
// ---------------------------------------------------------------------------
__global__ void k_prep_w1(const float* __restrict__ S,
                          const float* __restrict__ Pmu,
                          const float* __restrict__ Plv,
                          const float* __restrict__ Emu,
                          const float* __restrict__ Elv,
                          const float* __restrict__ R) {
    int r = blockIdx.x;      // k index 0..63
    int c = threadIdx.x;     // original col 0..511
    float v;
    if (c < 64) {
        v = S[r*64 + c];
    } else {
        int j = c - 64;
        float s = 0.f;
        if (j < 64)       { for (int k = 0; k < 64; k++) s += S[r*64+k] * Pmu[k*64 + j]; }
        else if (j < 128) { int jj = j-64;  for (int k = 0; k < 64; k++) s += S[r*64+k] * Plv[k*64 + jj]; }
        else if (j < 192) { int jj = j-128; for (int k = 0; k < 64; k++) s += S[r*64+k] * Emu[(128+k)*64 + jj]; }
        else if (j < 256) { int jj = j-192; for (int k = 0; k < 64; k++) s += S[r*64+k] * Elv[(128+k)*64 + jj]; }
        else              { int jj = j-256; for (int k = 0; k < 64; k++) s += S[r*64+k] * R[k*192 + jj]; }
        v = s;
    }
    int slot;
    if      (c < 64)  slot = 2*(128 + (c >> 1)) + (c & 1);
    else if (c < 128) slot = 2*(64 + (c - 64));
    else if (c < 192) slot = 2*(64 + (c - 128)) + 1;
    else if (c < 256) slot = 2*(c - 192);
    else if (c < 320) slot = 2*(c - 256) + 1;
    else              slot = 2*(160 + ((c - 320) >> 1)) + ((c - 320) & 1);
    g_W1p[(r >> 1) * 1024 + 2*slot + (r & 1)] = v;
}

// ---------------------------------------------------------------------------
// GEMM (round-2 inner loop, verbatim). ONLY change: grid swapped so the 5
// N-blocks sharing one A-tile are bid-adjacent -> co-resident -> A served
// from L2 instead of 5x DRAM re-reads.
// ---------------------------------------------------------------------------
#define GBM 128
#define GBN 64
#define SA_STRIDE 132
#define GEMM_SMEM_BYTES ((128*SA_STRIDE + 128*GBN) * 4)

__global__ void __launch_bounds__(256, 2) k_gemm_p(const float* __restrict__ x) {
    extern __shared__ float sm[];
    float* sA = sm;
    float* sB = sm + 128 * SA_STRIDE;
    int tid = threadIdx.x;
    int mb = blockIdx.y * GBM;    // swapped
    int nb = blockIdx.x * GBN;    // swapped

    for (int i = tid; i < 128 * 32; i += 256) {
        int r = i >> 5, c4 = (i & 31) << 2;
        float4 v = *(const float4*)(x + (mb + r) * F_ + c4);
        *(float4*)(sA + r * SA_STRIDE + c4) = v;
    }
    for (int i = tid; i < 128 * 16; i += 256) {
        int k = i >> 4, c4 = (i & 15) << 2;
        *(float4*)(sB + k * GBN + c4) = *(const float4*)(g_Wc + k * NPRE + nb + c4);
    }
    __syncthreads();

    int cg = tid & 7, rg = tid >> 3;
    int c0 = cg << 3, r0 = rg << 2;

    U64 acc[4][4];
#pragma unroll
    for (int i = 0; i < 4; i++)
#pragma unroll
        for (int j = 0; j < 4; j++) acc[i][j] = 0ull;

#pragma unroll 4
    for (int k = 0; k < 128; k++) {
        float a0 = sA[(r0+0)*SA_STRIDE + k];
        float a1 = sA[(r0+1)*SA_STRIDE + k];
        float a2 = sA[(r0+2)*SA_STRIDE + k];
        float a3 = sA[(r0+3)*SA_STRIDE + k];
        ulonglong2 b01 = *(const ulonglong2*)(sB + k*GBN + c0);
        ulonglong2 b23 = *(const ulonglong2*)(sB + k*GBN + c0 + 4);
        U64 p0 = pack2(a0), p1 = pack2(a1), p2 = pack2(a2), p3 = pack2(a3);
        fma2(acc[0][0], p0, b01.x); fma2(acc[0][1], p0, b01.y);
        fma2(acc[0][2], p0, b23.x); fma2(acc[0][3], p0, b23.y);
        fma2(acc[1][0], p1, b01.x); fma2(acc[1][1], p1, b01.y);
        fma2(acc[1][2], p1, b23.x); fma2(acc[1][3], p1, b23.y);
        fma2(acc[2][0], p2, b01.x); fma2(acc[2][1], p2, b01.y);
        fma2(acc[2][2], p2, b23.x); fma2(acc[2][3], p2, b23.y);
        fma2(acc[3][0], p3, b01.x); fma2(acc[3][1], p3, b01.y);
        fma2(acc[3][2], p3, b23.x); fma2(acc[3][3], p3, b23.y);
    }

#pragma unroll
    for (int i = 0; i < 4; i++) {
        float* dst = g_P + (mb + r0 + i) * NPRE + nb + c0;
        ulonglong2 v0; v0.x = acc[i][0]; v0.y = acc[i][1];
        *(ulonglong2*)dst = v0;
        ulonglong2 v1; v1.x = acc[i][2]; v1.y = acc[i][3];
        *(ulonglong2*)(dst + 4) = v1;
    }
}

// ---------------------------------------------------------------------------
// Recurrent kernel v4 (unchanged from round 4 — measured 1154 us)
// ---------------------------------------------------------------------------
#define OFF_W2  0
#define OFF_B0  12288
#define OFF_B1  12480
#define OFF_HP  12672
#define OFF_MH  12800
#define OFF_G   13184
#define OFF_H   13952
#define OFF_Z2  14080
#define RNN_SMEM_FLOATS 14336
#define RNN_SMEM_BYTES  (RNN_SMEM_FLOATS * 4)

__global__ void __launch_bounds__(256, 1) k_rnn(const float* __restrict__ gbias,
                                                const float* __restrict__ gruk,
                                                float* __restrict__ out) {
    extern __shared__ float sm[];
    float* sW2 = sm + OFF_W2;
    float* sB0 = sm + OFF_B0;
    float* sB1 = sm + OFF_B1;
    float* sHP = sm + OFF_HP;
    float* sMH = sm + OFF_MH;
    float* sG  = sm + OFF_G;
    float* sH  = sm + OFF_H;
    U64*   sZ2 = (U64*)(sm + OFF_Z2);

    int tid = threadIdx.x;
    int b0  = blockIdx.x * 2;

    for (int i = tid; i < (64*192)/4; i += 256)
        *(float4*)(sW2 + i*4) = *(const float4*)(gruk + 128*192 + i*4);
    if (tid < 96)
        *(float4*)(sB0 + tid*4) = *(const float4*)(gbias + tid*4);
    if (tid < 128) sH[tid] = 0.f;

    U64 w1a[32], w1b[32];
#pragma unroll
    for (int i = 0; i < 32; i++) {
        ulonglong2 v = *(const ulonglong2*)(g_W1p + i * 1024 + (tid << 2));
        w1a[i] = v.x; w1b[i] = v.y;
    }

    int re = tid >> 6, ue = tid & 63;
    int hf = (tid < 96) ? 0 : 1;
    int j2 = (tid < 96) ? tid : (tid - 96);
    int kb = hf << 5;

    const int SEQ = B_ * T_ * UU;
    const float* PZ0 = g_P + (long)(b0)     * T_ * NPRE + tid;
    const float* PZ1 = g_P + (long)(b0 + 1) * T_ * NPRE + tid;
    const float* PG  = g_P + (long)(b0 + re)* T_ * NPRE + 128 + ue;

    float cz0=0,cz1=0,cz2=0,cz3=0, cg0=0,cg1=0,cg2=0;
    if (tid < 64) {
        cz0 = PZ0[0];  cz1 = PZ0[64];
        cz2 = PZ1[0];  cz3 = PZ1[64];
    }
    if (tid < 128) {
        cg0 = PG[0];   cg1 = PG[64];  cg2 = PG[128];
    }
    __syncthreads();

#pragma unroll 1
    for (int t = 0; t < T_; t++) {
        int tn = (t + 1 < T_) ? (t + 1) : t;
        long offn = (long)tn * NPRE;
        float nz0=0,nz1=0,nz2=0,nz3=0, ng0=0,ng1=0,ng2=0;
        if (tid < 64) {
            nz0 = PZ0[offn];      nz1 = PZ0[offn + 64];
            nz2 = PZ1[offn];      nz3 = PZ1[offn + 64];
        }
        if (tid < 128) {
            ng0 = PG[offn];  ng1 = PG[offn + 64];  ng2 = PG[offn + 128];
        }

        const ulonglong2* h0 = (const ulonglong2*)(sH);
        const ulonglong2* h1 = (const ulonglong2*)(sH + 64);
        U64 a00 = 0ull, a01 = 0ull, a10 = 0ull, a11 = 0ull;
#pragma unroll
        for (int i = 0; i < 16; i++) {
            ulonglong2 ha = h0[i];
            ulonglong2 hb = h1[i];
            fma2(a00, ha.x, w1a[2*i]);   fma2(a01, ha.x, w1b[2*i]);
            fma2(a10, hb.x, w1a[2*i]);   fma2(a11, hb.x, w1b[2*i]);
            fma2(a00, ha.y, w1a[2*i+1]); fma2(a01, ha.y, w1b[2*i+1]);
            fma2(a10, hb.y, w1a[2*i+1]); fma2(a11, hb.y, w1b[2*i+1]);
        }
        float y00 = hsum2(a00), y01 = hsum2(a01);
        float y10 = hsum2(a10), y11 = hsum2(a11);

        if (tid < 64) {
            float qmu0 = y00 + cz0, qlv0 = y01 + cz1;
            float qmu1 = y10 + cz2, qlv1 = y11 + cz3;
            float z0 = 0.5f * __expf(qlv0) + qmu0;
            float z1 = 0.5f * __expf(qlv1) + qmu1;
            sZ2[tid]      = pack2(z0);
            sZ2[64 + tid] = pack2(z1);
            int base0 = (b0 * T_ + t) * UU + tid;
            int base1 = base0 + T_ * UU;
            out[base0]          = z0;
            out[base0 + SEQ]    = qmu0;
            out[base0 + 3*SEQ]  = qlv0;
            out[base1]          = z1;
            out[base1 + SEQ]    = qmu1;
            out[base1 + 3*SEQ]  = qlv1;
        } else if (tid < 128) {
            int u = tid - 64;
            int base0 = (b0 * T_ + t) * UU + u;
            int base1 = base0 + T_ * UU;
            out[base0 + 2*SEQ] = y00;
            out[base0 + 4*SEQ] = y01;
            out[base1 + 2*SEQ] = y10;
            out[base1 + 4*SEQ] = y11;
        } else if (tid < 160) {
            int j = tid - 128;
            *(float2*)(sHP + 2*j)       = make_float2(y00, y01);
            *(float2*)(sHP + 64 + 2*j)  = make_float2(y10, y11);
        } else {
            int j = tid - 160;
            *(float2*)(sMH + 2*j)        = make_float2(y00, y01);
            *(float2*)(sMH + 192 + 2*j)  = make_float2(y10, y11);
        }
        __syncthreads();

        if (tid < 192) {
            U64 g0 = 0ull, g1 = 0ull;
            const float* w2 = sW2 + (j2 << 1);
#pragma unroll
            for (int kk = 0; kk < 32; kk += 2) {
                int k = kb + kk;
                ulonglong2 z0 = *(const ulonglong2*)(sZ2 + k);
                ulonglong2 z1 = *(const ulonglong2*)(sZ2 + 64 + k);
                U64 wa = *(const U64*)(w2 + k * 192);
                U64 wb = *(const U64*)(w2 + (k+1) * 192);
                fma2(g0, z0.x, wa); fma2(g1, z1.x, wa);
                fma2(g0, z0.y, wb); fma2(g1, z1.y, wb);
            }
            *(U64*)(sG + ((hf << 1) + 0) * 192 + (j2 << 1)) = g0;
            *(U64*)(sG + ((hf << 1) + 1) * 192 + (j2 << 1)) = g1;
        }
        __syncthreads();

        if (tid < 128) {
            const float* Ga = sG + re * 192;
            const float* Gb = sG + (2 + re) * 192;
            float hp  = sHP[re * 64 + ue];
            float mhz = sMH[re * 192 + ue]        + sB1[ue];
            float mhr = sMH[re * 192 + 64 + ue]   + sB1[64 + ue];
            float mhh = sMH[re * 192 + 128 + ue]  + sB1[128 + ue];
            float mxz = cg0 + Ga[ue]        + Gb[ue]        + sB0[ue];
            float mxr = cg1 + Ga[64 + ue]   + Gb[64 + ue]   + sB0[64 + ue];
            float mxh = cg2 + Ga[128 + ue]  + Gb[128 + ue]  + sB0[128 + ue];
            float zt = sigmoid_f(mxz + mhz);
            float rt = sigmoid_f(mxr + mhr);
            float hh = tanh_exp(mxh + rt * mhh);
            sH[re * 64 + ue] = zt * hp + (1.f - zt) * hh;
        }
        __syncthreads();

        cz0 = nz0; cz1 = nz1; cz2 = nz2; cz3 = nz3;
        cg0 = ng0; cg1 = ng1; cg2 = ng2;
    }
}

// ---------------------------------------------------------------------------
extern "C" void kernel_launch(void* const* d_in, const int* in_sizes, int n_in,
                              void* d_out, int out_size) {
    const float* x   = (const float*)d_in[0];
    const float* Win = (const float*)d_in[1];
    const float* S   = (const float*)d_in[2];
    const float* Emu = (const float*)d_in[3];
    const float* Elv = (const float*)d_in[4];
    const float* Pmu = (const float*)d_in[5];
    const float* Plv = (const float*)d_in[6];
    const float* Wg  = (const float*)d_in[7];
    const float* R   = (const float*)d_in[8];
    const float* gb  = (const float*)d_in[9];

    cudaFuncSetAttribute(k_gemm_p, cudaFuncAttributeMaxDynamicSharedMemorySize, GEMM_SMEM_BYTES);
    cudaFuncSetAttribute(k_rnn,    cudaFuncAttributeMaxDynamicSharedMemorySize, RNN_SMEM_BYTES);

    k_prep_wc<<<128, 320>>>(Win, Emu, Elv, Wg);
    k_prep_w1<<<64, 512>>>(S, Pmu, Plv, Emu, Elv, R);

    dim3 gg(5, 2048);   // N-tiles fastest: same-A blocks adjacent -> L2 reuse
    k_gemm_p<<<gg, 256, GEMM_SMEM_BYTES>>>(x);

    k_rnn<<<128, 256, RNN_SMEM_BYTES>>>(gb, Wg, (float*)d_out);
}